// round 6
// baseline (speedup 1.0000x reference)
#include <cuda_runtime.h>
#include <cuda_bf16.h>
#include <cstdint>

#define T_STEPS 1024
#define BATCH   128
#define FEAT    88
#define HID     1024
#define CLS     88
#define KTOT    1112          // HID + FEAT
#define KP      1152          // padded K
#define WS_STRIDE 1160        // SMEM row stride (halfs) for resident W slice
#define NCTA    128
#define NTHR    256
#define MT      64            // batch rows per CTA
#define UPC     16            // hidden units per CTA -> 64 gate cols
#define CW      128           // A chunk width (K cols per chunk)
#define ASTR    136           // A-tile row stride in halfs (128 + 8 pad)
#define NBUF    3             // A-stage ring buffers
#define NSEQ    9             // chunks per step: 1 x-chunk + 8 h-chunks
#define GSM_STRIDE 68
#define FC_ASTR 72

// ---------------- device globals ----------------
__device__ __nv_bfloat16 g_Wc[(size_t)4096 * KP];                  // combined [W_hh | W_ih | pad], bf16
__device__ __nv_bfloat16 g_Wfcb[(size_t)CLS * HID];                // W_fc bf16
__device__ float         g_bsum[4096];                             // b_ih + b_hh
__device__ __nv_bfloat16 g_xb[(size_t)T_STEPS * BATCH * FEAT];     // x in bf16
__device__ __nv_bfloat16 g_h[2][BATCH * HID];                      // double-buffered hidden state
__device__ __nv_bfloat16 g_Hall[(size_t)T_STEPS * BATCH * HID];    // all h_t for FC
__device__ int           g_flag[NCTA * 4];                         // per-CTA step flags (16B padded)

// ---------------- helpers ----------------
__device__ __forceinline__ unsigned smem_u32(const void* p) {
    return (unsigned)__cvta_generic_to_shared(p);
}
__device__ __forceinline__ float sigmoidf_(float x) {
    return 1.0f / (1.0f + __expf(-x));
}
__device__ __forceinline__ float tanhf_(float x) {
    float ax = fabsf(x);
    float e  = __expf(-2.0f * ax);
    float r  = (1.0f - e) / (1.0f + e);
    return (x < 0.0f) ? -r : r;
}

#define MMA_BF16(ACC, A0, A1, A2, A3, B0, B1)                                             \
    asm volatile(                                                                         \
        "mma.sync.aligned.m16n8k16.row.col.f32.bf16.bf16.f32 "                            \
        "{%0,%1,%2,%3}, {%4,%5,%6,%7}, {%8,%9}, {%0,%1,%2,%3};\n"                         \
        : "+f"((ACC)[0]), "+f"((ACC)[1]), "+f"((ACC)[2]), "+f"((ACC)[3])                  \
        : "r"(A0), "r"(A1), "r"(A2), "r"(A3), "r"(B0), "r"(B1))

#define LDMATRIX_X4(R0, R1, R2, R3, ADDR)                                                 \
    asm volatile("ldmatrix.sync.aligned.m8n8.x4.shared.b16 {%0,%1,%2,%3}, [%4];\n"        \
                 : "=r"(R0), "=r"(R1), "=r"(R2), "=r"(R3) : "r"(ADDR))

#define LDS64(R0, R1, ADDR)                                                               \
    asm volatile("ld.shared.v2.u32 {%0,%1}, [%2];" : "=r"(R0), "=r"(R1) : "r"(ADDR))

#define CP_ASYNC16(DST, SRC)                                                              \
    asm volatile("cp.async.cg.shared.global [%0], [%1], 16;\n" :: "r"(DST), "l"(SRC))
#define CP_ASYNC16_ZFILL(DST, SRC)                                                        \
    asm volatile("cp.async.cg.shared.global [%0], [%1], 16, %2;\n"                        \
                 :: "r"(DST), "l"(SRC), "r"(0))
#define CP_COMMIT  asm volatile("cp.async.commit_group;\n")
#define CP_WAIT(N) asm volatile("cp.async.wait_group %0;\n" :: "n"(N))

// ---------------- prep kernels ----------------
__global__ void init_kernel() {
    int idx = blockIdx.x * blockDim.x + threadIdx.x;
    uint4 z = make_uint4(0u, 0u, 0u, 0u);
    for (int i = idx; i < 32768; i += gridDim.x * blockDim.x)
        reinterpret_cast<uint4*>(g_h)[i] = z;
    if (idx < NCTA * 4) g_flag[idx] = 0;
}

__global__ void prep_wc_kernel(const float* __restrict__ Wih, const float* __restrict__ Whh) {
    size_t idx = (size_t)blockIdx.x * blockDim.x + threadIdx.x;
    size_t total = (size_t)4096 * KP;
    if (idx >= total) return;
    int n = (int)(idx / KP);
    int k = (int)(idx % KP);
    float v = 0.0f;
    if (k < HID)        v = Whh[(size_t)n * HID + k];
    else if (k < KTOT)  v = Wih[(size_t)n * FEAT + (k - HID)];
    g_Wc[idx] = __float2bfloat16(v);
}

__global__ void prep_misc_kernel(const float* __restrict__ bih, const float* __restrict__ bhh,
                                 const float* __restrict__ Wfc) {
    int idx = blockIdx.x * blockDim.x + threadIdx.x;
    if (idx < 4096) g_bsum[idx] = bih[idx] + bhh[idx];
    int widx = idx - 4096;
    if (widx >= 0 && widx < CLS * HID) g_Wfcb[widx] = __float2bfloat16(Wfc[widx]);
}

__global__ void prep_x_kernel(const float* __restrict__ x) {
    size_t idx = (size_t)blockIdx.x * blockDim.x + threadIdx.x;
    size_t total = (size_t)T_STEPS * BATCH * FEAT;
    if (idx < total) g_xb[idx] = __float2bfloat16(x[idx]);
}

// ---------------- persistent LSTM step kernel (wavefront sync) ----------------
// 128 CTAs, 256 threads. CTA (m,n): m = bid&1 (64 batch rows), n = bid>>1
// (16 units -> 64 gate cols). Batch halves fully decoupled. Per step:
// 9 chunks of K=128 (1 x-chunk + 8 h-chunks, rotated so own column group
// comes first). h-chunk c needs only its 8 same-half producer CTAs ->
// per-chunk flag waits (preloaded at step start; fast path = 1 syncthreads_count).
__global__ void __launch_bounds__(NTHR, 1)
lstm_kernel(const int* __restrict__ lens)
{
    extern __shared__ char smem_raw[];
    __nv_bfloat16* Ws  = reinterpret_cast<__nv_bfloat16*>(smem_raw);        // 64 * WS_STRIDE
    __nv_bfloat16* As  = Ws + 64 * WS_STRIDE;                               // NBUF * 64 * ASTR
    float* gsm         = reinterpret_cast<float*>(As + NBUF * 64 * ASTR);   // 64 * GSM_STRIDE
    float* bias_s      = gsm + 64 * GSM_STRIDE;                             // 64
    int*   len_s       = reinterpret_cast<int*>(bias_s + 64);               // 64

    const int tid   = threadIdx.x;
    const int bid   = blockIdx.x;
    const int cta_m = bid & 1;
    const int cta_n = bid >> 1;
    const int b0    = cta_m * MT;
    const int hid0  = cta_n * UPC;
    const int g0    = cta_n >> 3;          // own column group (0..7)

    // Resident W slice, k-permuted within each 16-half group so a B fragment
    // is one ld.shared.v2.u32: pair q holds source pair (q>>1)+((q&1)<<2).
    for (int i = tid; i < 64 * (KP / 2); i += NTHR) {
        int n = i / (KP / 2), j = i % (KP / 2);
        int g16 = j >> 3, q = j & 7;
        int sp  = (q >> 1) + ((q & 1) << 2);
        int g = n >> 4, u = n & 15;
        const unsigned* src = reinterpret_cast<const unsigned*>(
                g_Wc + (size_t)(g * HID + hid0 + u) * KP);
        reinterpret_cast<unsigned*>(Ws + (size_t)n * WS_STRIDE)[j] = src[g16 * 8 + sp];
    }
    if (tid < 64) {
        int g = tid >> 4, u = tid & 15;
        bias_s[tid] = g_bsum[g * HID + hid0 + u];
    } else if (tid < 128) {
        len_s[tid - 64] = lens[b0 + (tid - 64)];
    }
    __syncthreads();

    const int lane = tid & 31, wid = tid >> 5;
    const int wm = wid & 1;        // 0..1 : 32 rows
    const int wn = wid >> 1;       // 0..3 : 16 cols
    const int eu  = tid & 15;
    const int eb0 = tid >> 4;

    const unsigned ws_u = smem_u32(Ws);
    const unsigned as_u = smem_u32(As);

    // flag-watch assignment: tid<64. rotpos rp = tid>>3 (0..7) covers the
    // h-chunk at sequence position rp+1; producer j = tid&7.
    // chunk c = 1 + ((g0 + rp)&7); producer cta_n = (c-1)*8 + j (same half).
    const int*  my_fp  = (tid < 64)
        ? &g_flag[(((((g0 + (tid >> 3)) & 7) * 8 + (tid & 7)) << 1) | cta_m) << 2]
        : &g_flag[0];
    const int   my_rp  = tid >> 3;
    const bool  watcher = (tid < 64);

    float hreg[4] = {0.f, 0.f, 0.f, 0.f};
    float creg[4] = {0.f, 0.f, 0.f, 0.f};

    for (int t = 0; t < T_STEPS; ++t) {
        const __nv_bfloat16* __restrict__ h_cur = g_h[t & 1];
        __nv_bfloat16* __restrict__ h_nxt = g_h[(t & 1) ^ 1];

        // preload all producer flags for this step (MLP-overlapped)
        int fv = watcher ? __ldcg(my_fp) : 0x7fffffff;

        // stage seq chunk s into ring buffer s%NBUF.  chunk(s): s==0 -> x
        // (K cols 1024..1151), else 1+((g0+s-1)&7) -> K cols (c-1)*128.
        auto stage = [&](int s) {
            const int c = (s == 0) ? 0 : (1 + ((g0 + s - 1) & 7));
            unsigned dstb = as_u + (unsigned)((s % NBUF) * 64 * ASTR * 2);
#pragma unroll
            for (int r = 0; r < 4; ++r) {
                int slot = tid + r * NTHR;           // 1024 slots = 64 rows x 16 seg
                int row = slot >> 4, c16 = slot & 15;
                unsigned dst = dstb + (unsigned)((row * ASTR + c16 * 8) * 2);
                if (c > 0) {
                    CP_ASYNC16(dst, h_cur + (size_t)(b0 + row) * HID + (c - 1) * CW + c16 * 8);
                } else {
                    int f = c16 * 8;
                    if (f + 8 <= FEAT) {
                        CP_ASYNC16(dst, g_xb + ((size_t)t * BATCH + b0 + row) * FEAT + f);
                    } else {
                        CP_ASYNC16_ZFILL(dst, g_xb);
                    }
                }
            }
            CP_COMMIT;
        };

        // wait (barrier + flag check) for seq chunk s's producers: rp = s-1
        auto waitgrp = [&](int s) {
            const int rp = s - 1;
            const bool need = watcher && (my_rp == rp);
            for (;;) {
                int ok = (!need) || (fv >= t);
                if (__syncthreads_count(ok) == NTHR) break;
                if (need && fv < t) fv = __ldcg(my_fp);
            }
        };

        // prologue: x chunk free; first h chunk gated by its group
        stage(0);
        waitgrp(1);
        stage(1);

        float acc[2][2][4];
#pragma unroll
        for (int a = 0; a < 2; ++a)
#pragma unroll
            for (int b = 0; b < 2; ++b)
#pragma unroll
                for (int c = 0; c < 4; ++c) acc[a][b][c] = 0.f;

        for (int s = 0; s < NSEQ; ++s) {
            // group s's cp.async data complete (1 younger group may remain)
            if (s < NSEQ - 1) { CP_WAIT(1); } else { CP_WAIT(0); }
            // barrier (+ producer check for chunk s+2), then prefetch it
            if (s + 2 <= NSEQ - 1) {
                waitgrp(s + 2);        // doubles as the data-visibility barrier
                stage(s + 2);
            } else {
                __syncthreads();
            }

            const int c    = (s == 0) ? 0 : (1 + ((g0 + s - 1) & 7));
            const int kcol = (c == 0) ? HID : ((c - 1) * CW);
            const unsigned abase = as_u + (unsigned)((s % NBUF) * 64 * ASTR * 2);
#pragma unroll
            for (int ks = 0; ks < 8; ++ks) {
                const int kk = ks * 16;
                const int kg = kcol + kk;
                unsigned a[2][4];
#pragma unroll
                for (int mi = 0; mi < 2; ++mi) {
                    unsigned addr = abase +
                        (unsigned)(((wm * 32 + mi * 16 + (lane & 15)) * ASTR +
                                    kk + ((lane >> 4) << 3)) * 2);
                    LDMATRIX_X4(a[mi][0], a[mi][1], a[mi][2], a[mi][3], addr);
                }
#pragma unroll
                for (int nf = 0; nf < 2; ++nf) {
                    int n = wn * 16 + nf * 8 + (lane >> 2);
                    unsigned baddr = ws_u +
                        (unsigned)((n * WS_STRIDE + kg) * 2) + ((lane & 3) << 3);
                    unsigned b0r, b1r;
                    LDS64(b0r, b1r, baddr);
#pragma unroll
                    for (int mi = 0; mi < 2; ++mi) {
                        MMA_BF16(acc[mi][nf], a[mi][0], a[mi][1], a[mi][2], a[mi][3], b0r, b1r);
                    }
                }
            }
        }
        __syncthreads();

        // accumulators -> gsm for cross-warp gate regrouping
#pragma unroll
        for (int mi = 0; mi < 2; ++mi) {
            int r = wm * 32 + mi * 16 + (lane >> 2);
#pragma unroll
            for (int nf = 0; nf < 2; ++nf) {
                int c = wn * 16 + nf * 8 + ((lane & 3) << 1);
                gsm[r * GSM_STRIDE + c]           = acc[mi][nf][0];
                gsm[r * GSM_STRIDE + c + 1]       = acc[mi][nf][1];
                gsm[(r + 8) * GSM_STRIDE + c]     = acc[mi][nf][2];
                gsm[(r + 8) * GSM_STRIDE + c + 1] = acc[mi][nf][3];
            }
        }
        __syncthreads();

        // LSTM cell: thread owns (b_local = eb0 + 16p, unit = eu)
#pragma unroll
        for (int p = 0; p < 4; ++p) {
            int bl = eb0 + p * 16;
            float gi = gsm[bl * GSM_STRIDE + eu]        + bias_s[eu];
            float gf = gsm[bl * GSM_STRIDE + 16 + eu]   + bias_s[16 + eu];
            float gg = gsm[bl * GSM_STRIDE + 32 + eu]   + bias_s[32 + eu];
            float go = gsm[bl * GSM_STRIDE + 48 + eu]   + bias_s[48 + eu];
            float ii = sigmoidf_(gi);
            float ff = sigmoidf_(gf);
            float gt = tanhf_(gg);
            float oo = sigmoidf_(go);
            float cn = ff * creg[p] + ii * gt;
            float hn = oo * tanhf_(cn);
            bool  m  = t < len_s[bl];
            float h2 = m ? hn : hreg[p];
            creg[p]  = m ? cn : creg[p];
            hreg[p]  = h2;
            __nv_bfloat16 hb = __float2bfloat16(h2);
            int bg = b0 + bl;
            int j  = hid0 + eu;
            h_nxt[bg * HID + j] = hb;
            g_Hall[((size_t)t * BATCH + bg) * HID + j] = hb;
        }

        // publish step t
        __threadfence();
        __syncthreads();
        if (tid == 0) __stcg(&g_flag[bid << 2], t + 1);
    }
}

// ---------------- FC head: logits + binary expansion ----------------
__global__ void __launch_bounds__(128)
fc_kernel(const int* __restrict__ lens, const float* __restrict__ bfc,
          float* __restrict__ out)
{
    __shared__ __nv_bfloat16 As[64 * FC_ASTR];
    __shared__ __nv_bfloat16 Bs[88 * FC_ASTR];

    const int tid  = threadIdx.x;
    const int lane = tid & 31, wid = tid >> 5;
    const int r0   = blockIdx.x * 64;   // rows of H_all (tb = t*128 + b)

    float acc[11][4];
#pragma unroll
    for (int i = 0; i < 11; ++i)
#pragma unroll
        for (int j = 0; j < 4; ++j) acc[i][j] = 0.f;

    const unsigned as_u = smem_u32(As);
    const unsigned bs_u = smem_u32(Bs);

    for (int ch = 0; ch < 16; ++ch) {
        __syncthreads();
        const int k0 = ch * 64;
        for (int i = tid; i < 512; i += 128) {          // A: 64 rows x 8 uint4
            int row = i >> 3, c8 = i & 7;
            uint4 v = *(reinterpret_cast<const uint4*>(
                    g_Hall + (size_t)(r0 + row) * HID + k0) + c8);
            *(reinterpret_cast<uint4*>(As + row * FC_ASTR) + c8) = v;
        }
        for (int i = tid; i < 704; i += 128) {          // B: 88 rows x 8 uint4
            int row = i >> 3, c8 = i & 7;
            uint4 v = *(reinterpret_cast<const uint4*>(
                    g_Wfcb + (size_t)row * HID + k0) + c8);
            *(reinterpret_cast<uint4*>(Bs + row * FC_ASTR) + c8) = v;
        }
        __syncthreads();
#pragma unroll
        for (int ks = 0; ks < 4; ++ks) {
            int kk = ks * 16;
            unsigned a0, a1, a2, a3;
            unsigned addr = as_u +
                (unsigned)(((wid * 16 + (lane & 15)) * FC_ASTR + kk + ((lane >> 4) << 3)) * 2);
            LDMATRIX_X4(a0, a1, a2, a3, addr);
#pragma unroll
            for (int nf = 0; nf < 11; ++nf) {
                int n = nf * 8 + (lane >> 2);
                unsigned baddr = bs_u +
                    (unsigned)((n * FC_ASTR + kk + ((lane & 3) << 1)) * 2);
                unsigned b0r, b1r;
                asm volatile("ld.shared.b32 %0, [%1];" : "=r"(b0r) : "r"(baddr));
                asm volatile("ld.shared.b32 %0, [%1];" : "=r"(b1r) : "r"(baddr + 16));
                MMA_BF16(acc[nf], a0, a1, a2, a3, b0r, b1r);
            }
        }
    }

#pragma unroll
    for (int half = 0; half < 2; ++half) {
        int r  = wid * 16 + (lane >> 2) + half * 8;
        int tb = r0 + r;
        int t  = tb >> 7;
        int b  = tb & 127;
        bool m = t < __ldg(lens + b);
        size_t obase = ((size_t)b * T_STEPS + t) * CLS * 2;
#pragma unroll
        for (int nf = 0; nf < 11; ++nf) {
            int c = nf * 8 + ((lane & 3) << 1);
            float l0 = acc[nf][half * 2 + 0] + __ldg(bfc + c);
            float l1 = acc[nf][half * 2 + 1] + __ldg(bfc + c + 1);
            if (!m) { l0 = 0.f; l1 = 0.f; }
            float4 v = make_float4(l0, 1.f - l0, l1, 1.f - l1);
            *reinterpret_cast<float4*>(out + obase + (size_t)c * 2) = v;
        }
    }
}

// ---------------- launch ----------------
extern "C" void kernel_launch(void* const* d_in, const int* in_sizes, int n_in,
                              void* d_out, int out_size) {
    const float* x    = (const float*)d_in[0];
    const int*   lens = (const int*)d_in[1];    // int32 (JAX x64 disabled)
    const float* Wih  = (const float*)d_in[2];
    const float* Whh  = (const float*)d_in[3];
    const float* bih  = (const float*)d_in[4];
    const float* bhh  = (const float*)d_in[5];
    const float* Wfc  = (const float*)d_in[6];
    const float* bfc  = (const float*)d_in[7];
    float*       out  = (float*)d_out;
    (void)in_sizes; (void)n_in; (void)out_size;

    init_kernel<<<64, 256>>>();
    {
        size_t tot = (size_t)4096 * KP;
        prep_wc_kernel<<<(unsigned)((tot + 255) / 256), 256>>>(Wih, Whh);
    }
    prep_misc_kernel<<<(4096 + CLS * HID + 255) / 256, 256>>>(bih, bhh, Wfc);
    {
        size_t tot = (size_t)T_STEPS * BATCH * FEAT;
        prep_x_kernel<<<(unsigned)((tot + 255) / 256), 256>>>(x);
    }

    int smem = 64 * WS_STRIDE * 2          // resident W slice      (148480)
             + NBUF * 64 * ASTR * 2        // A-stage ring          (52224)
             + 64 * GSM_STRIDE * 4         // gate exchange         (17408)
             + 64 * 4 + 64 * 4;            // bias + lengths
    cudaFuncSetAttribute(lstm_kernel, cudaFuncAttributeMaxDynamicSharedMemorySize, smem);
    lstm_kernel<<<NCTA, NTHR, smem>>>(lens);

    fc_kernel<<<(T_STEPS * BATCH) / 64, 128>>>(lens, bfc, out);
}

// round 7
// speedup vs baseline: 1.2203x; 1.2203x over previous
#include <cuda_runtime.h>
#include <cuda_bf16.h>
#include <cstdint>

#define T_STEPS 1024
#define BATCH   128
#define FEAT    88
#define HID     1024
#define CLS     88
#define KTOT    1112          // HID + FEAT
#define KP      1152          // padded K
#define WS_STRIDE 1168        // resident-W row stride (halfs): 8-bank shift/row -> LDS64 conflict-free
#define NCTA    128
#define NTHR    256
#define MT      64            // batch rows per CTA
#define UPC     16            // hidden units per CTA -> 64 gate cols
#define CW      128           // A chunk width (K cols)
#define NSEQ    9             // chunks per step (1 x + 8 h)
#define ASTR    136           // A-tile row stride (halfs)
#define NBUF    4             // A-stage ring buffers
#define GSM_STRIDE 68
#define FC_ASTR 72

// ---------------- device globals ----------------
__device__ __nv_bfloat16 g_Wc[(size_t)4096 * KP];                  // combined [W_hh | W_ih | pad], bf16
__device__ __nv_bfloat16 g_Wfcb[(size_t)CLS * HID];                // W_fc bf16
__device__ float         g_bsum[4096];                             // b_ih + b_hh
__device__ __nv_bfloat16 g_xb[(size_t)T_STEPS * BATCH * FEAT];     // x in bf16
__device__ __nv_bfloat16 g_h[2][BATCH * HID];                      // double-buffered hidden state
__device__ __nv_bfloat16 g_Hall[(size_t)T_STEPS * BATCH * HID];    // all h_t for FC
__device__ int           g_flag[NCTA * 4];                         // per-CTA step flags (16B padded)

// ---------------- helpers ----------------
__device__ __forceinline__ unsigned smem_u32(const void* p) {
    return (unsigned)__cvta_generic_to_shared(p);
}
__device__ __forceinline__ float sigmoidf_(float x) {
    return 1.0f / (1.0f + __expf(-x));
}
__device__ __forceinline__ float tanhf_(float x) {
    float ax = fabsf(x);
    float e  = __expf(-2.0f * ax);
    float r  = (1.0f - e) / (1.0f + e);
    return (x < 0.0f) ? -r : r;
}

#define MMA_BF16(ACC, A0, A1, A2, A3, B0, B1)                                             \
    asm volatile(                                                                         \
        "mma.sync.aligned.m16n8k16.row.col.f32.bf16.bf16.f32 "                            \
        "{%0,%1,%2,%3}, {%4,%5,%6,%7}, {%8,%9}, {%0,%1,%2,%3};\n"                         \
        : "+f"((ACC)[0]), "+f"((ACC)[1]), "+f"((ACC)[2]), "+f"((ACC)[3])                  \
        : "r"(A0), "r"(A1), "r"(A2), "r"(A3), "r"(B0), "r"(B1))

#define LDMATRIX_X4(R0, R1, R2, R3, ADDR)                                                 \
    asm volatile("ldmatrix.sync.aligned.m8n8.x4.shared.b16 {%0,%1,%2,%3}, [%4];\n"        \
                 : "=r"(R0), "=r"(R1), "=r"(R2), "=r"(R3) : "r"(ADDR))

#define LDS64(R0, R1, ADDR)                                                               \
    asm volatile("ld.shared.v2.u32 {%0,%1}, [%2];" : "=r"(R0), "=r"(R1) : "r"(ADDR))

#define CP_ASYNC16(DST, SRC)                                                              \
    asm volatile("cp.async.cg.shared.global [%0], [%1], 16;\n" :: "r"(DST), "l"(SRC))
#define CP_ASYNC16_ZFILL(DST, SRC)                                                        \
    asm volatile("cp.async.cg.shared.global [%0], [%1], 16, %2;\n"                        \
                 :: "r"(DST), "l"(SRC), "r"(0))
#define CP_COMMIT  asm volatile("cp.async.commit_group;\n")
#define CP_WAIT(N) asm volatile("cp.async.wait_group %0;\n" :: "n"(N))

// ---------------- prep kernels (merged so lstm_kernel is the 4th launch) ----------------
__global__ void init_kernel() {
    int idx = blockIdx.x * blockDim.x + threadIdx.x;
    uint4 z = make_uint4(0u, 0u, 0u, 0u);
    for (int i = idx; i < 32768; i += gridDim.x * blockDim.x)
        reinterpret_cast<uint4*>(g_h)[i] = z;
    if (idx < NCTA * 4) g_flag[idx] = 0;
}

__global__ void prep_all_kernel(const float* __restrict__ Wih, const float* __restrict__ Whh,
                                const float* __restrict__ bih, const float* __restrict__ bhh,
                                const float* __restrict__ Wfc) {
    size_t idx = (size_t)blockIdx.x * blockDim.x + threadIdx.x;
    size_t total = (size_t)4096 * KP;
    if (idx < total) {
        int n = (int)(idx / KP);
        int k = (int)(idx % KP);
        float v = 0.0f;
        if (k < HID)        v = Whh[(size_t)n * HID + k];
        else if (k < KTOT)  v = Wih[(size_t)n * FEAT + (k - HID)];
        g_Wc[idx] = __float2bfloat16(v);
    }
    if (idx < 4096) g_bsum[idx] = bih[idx] + bhh[idx];
    if (idx < (size_t)CLS * HID) g_Wfcb[idx] = __float2bfloat16(Wfc[idx]);
}

__global__ void prep_x_kernel(const float* __restrict__ x) {
    size_t idx = (size_t)blockIdx.x * blockDim.x + threadIdx.x;
    size_t total = (size_t)T_STEPS * BATCH * FEAT;
    if (idx < total) g_xb[idx] = __float2bfloat16(x[idx]);
}

// ---------------- persistent LSTM step kernel ----------------
// 128 CTAs, 256 threads. CTA (m,n): m = bid&1 (64 batch rows), n = bid>>1
// (16 units -> 64 gate cols). Single per-step barrier on the 64 SAME-HALF
// producer flags (batch halves fully decoupled). 9 K-chunks of 128
// (chunk 0 = x cols 1024..1151 staged pre-barrier; chunks 1..8 = h).
// cp.async 4-buffer ring, wait-distance 2. gsm aliases ring buffer 1
// (last read at chunk 5, reused only after the chunk loop).
__global__ void __launch_bounds__(NTHR, 1)
lstm_kernel(const int* __restrict__ lens)
{
    extern __shared__ char smem_raw[];
    __nv_bfloat16* Ws  = reinterpret_cast<__nv_bfloat16*>(smem_raw);        // 64 * WS_STRIDE
    __nv_bfloat16* As  = Ws + 64 * WS_STRIDE;                               // NBUF * 64 * ASTR
    float* gsm         = reinterpret_cast<float*>(As + 64 * ASTR);          // aliases ring buf 1
    float* bias_s      = reinterpret_cast<float*>(As + NBUF * 64 * ASTR);   // 64
    int*   len_s       = reinterpret_cast<int*>(bias_s + 64);               // 64

    const int tid   = threadIdx.x;
    const int bid   = blockIdx.x;
    const int cta_m = bid & 1;
    const int cta_n = bid >> 1;
    const int b0    = cta_m * MT;
    const int hid0  = cta_n * UPC;

    // Resident W slice, k-permuted within each 16-half group so a B fragment
    // is one ld.shared.v2.u32: pair q holds source pair (q>>1)+((q&1)<<2).
    for (int i = tid; i < 64 * (KP / 2); i += NTHR) {
        int n = i / (KP / 2), j = i % (KP / 2);
        int g16 = j >> 3, q = j & 7;
        int sp  = (q >> 1) + ((q & 1) << 2);
        int g = n >> 4, u = n & 15;
        const unsigned* src = reinterpret_cast<const unsigned*>(
                g_Wc + (size_t)(g * HID + hid0 + u) * KP);
        reinterpret_cast<unsigned*>(Ws + (size_t)n * WS_STRIDE)[j] = src[g16 * 8 + sp];
    }
    if (tid < 64) {
        int g = tid >> 4, u = tid & 15;
        bias_s[tid] = g_bsum[g * HID + hid0 + u];
    } else if (tid < 128) {
        len_s[tid - 64] = lens[b0 + (tid - 64)];
    }
    __syncthreads();

    const int lane = tid & 31, wid = tid >> 5;
    const int wm = wid & 1;        // 0..1 : 32 rows
    const int wn = wid >> 1;       // 0..3 : 16 cols
    const int eu  = tid & 15;
    const int eb0 = tid >> 4;

    const unsigned ws_u = smem_u32(Ws);
    const unsigned as_u = smem_u32(As);

    // barrier watchers: tid<64 each watch same-half producer (cta_n'=tid, half=cta_m)
    const bool watcher = (tid < 64);
    const int* my_fp   = &g_flag[(((tid & 63) << 1) | cta_m) << 2];

    float hreg[4] = {0.f, 0.f, 0.f, 0.f};
    float creg[4] = {0.f, 0.f, 0.f, 0.f};

    for (int t = 0; t < T_STEPS; ++t) {
        const __nv_bfloat16* __restrict__ h_cur = g_h[t & 1];
        __nv_bfloat16* __restrict__ h_nxt = g_h[(t & 1) ^ 1];

        // stage chunk s into ring buf s&3. s==0 -> x (cols 1024..), else h.
        auto stage = [&](int s) {
            unsigned dstb = as_u + (unsigned)((s & 3) * 64 * ASTR * 2);
#pragma unroll
            for (int r = 0; r < 4; ++r) {
                int slot = tid + r * NTHR;           // 1024 slots = 64 rows x 16 seg
                int row = slot >> 4, c16 = slot & 15;
                unsigned dst = dstb + (unsigned)((row * ASTR + c16 * 8) * 2);
                if (s >= 1) {
                    CP_ASYNC16(dst, h_cur + (size_t)(b0 + row) * HID + (s - 1) * CW + c16 * 8);
                } else {
                    int f = c16 * 8;
                    if (f + 8 <= FEAT) {
                        CP_ASYNC16(dst, g_xb + ((size_t)t * BATCH + b0 + row) * FEAT + f);
                    } else {
                        CP_ASYNC16_ZFILL(dst, g_xb);
                    }
                }
            }
            CP_COMMIT;
        };

        // x chunk is h-independent: stage before the barrier
        stage(0);

        // half-barrier: the 64 same-half CTAs must have published step t-1
        if (t > 0) {
            int fv = watcher ? __ldcg(my_fp) : 0x7fffffff;
            for (;;) {
                if (__syncthreads_count(fv >= t) == NTHR) break;
                if (watcher && fv < t) fv = __ldcg(my_fp);
            }
        }

        stage(1);
        stage(2);

        float acc[2][2][4];
#pragma unroll
        for (int a = 0; a < 2; ++a)
#pragma unroll
            for (int b = 0; b < 2; ++b)
#pragma unroll
                for (int c = 0; c < 4; ++c) acc[a][b][c] = 0.f;

        for (int s = 0; s < NSEQ; ++s) {
            // complete chunk s (leave up to 2 younger groups in flight)
            if (s < NSEQ - 2)      { CP_WAIT(2); }
            else if (s == NSEQ - 2){ CP_WAIT(1); }
            else                   { CP_WAIT(0); }
            __syncthreads();
            if (s + 3 < NSEQ) stage(s + 3);   // ring buf (s+3)&3 free (compute s-1 done)

            const int kcol = (s == 0) ? HID : ((s - 1) * CW);
            const unsigned abase = as_u + (unsigned)((s & 3) * 64 * ASTR * 2);
#pragma unroll
            for (int ks = 0; ks < 8; ++ks) {
                const int kk = ks * 16;
                const int kg = kcol + kk;
                unsigned a[2][4];
#pragma unroll
                for (int mi = 0; mi < 2; ++mi) {
                    unsigned addr = abase +
                        (unsigned)(((wm * 32 + mi * 16 + (lane & 15)) * ASTR +
                                    kk + ((lane >> 4) << 3)) * 2);
                    LDMATRIX_X4(a[mi][0], a[mi][1], a[mi][2], a[mi][3], addr);
                }
#pragma unroll
                for (int nf = 0; nf < 2; ++nf) {
                    int n = wn * 16 + nf * 8 + (lane >> 2);
                    unsigned baddr = ws_u +
                        (unsigned)((n * WS_STRIDE + kg) * 2) + ((lane & 3) << 3);
                    unsigned b0r, b1r;
                    LDS64(b0r, b1r, baddr);
#pragma unroll
                    for (int mi = 0; mi < 2; ++mi) {
                        MMA_BF16(acc[mi][nf], a[mi][0], a[mi][1], a[mi][2], a[mi][3], b0r, b1r);
                    }
                }
            }
        }
        __syncthreads();

        // accumulators -> gsm (aliases ring buf 1; all computes done)
#pragma unroll
        for (int mi = 0; mi < 2; ++mi) {
            int r = wm * 32 + mi * 16 + (lane >> 2);
#pragma unroll
            for (int nf = 0; nf < 2; ++nf) {
                int c = wn * 16 + nf * 8 + ((lane & 3) << 1);
                gsm[r * GSM_STRIDE + c]           = acc[mi][nf][0];
                gsm[r * GSM_STRIDE + c + 1]       = acc[mi][nf][1];
                gsm[(r + 8) * GSM_STRIDE + c]     = acc[mi][nf][2];
                gsm[(r + 8) * GSM_STRIDE + c + 1] = acc[mi][nf][3];
            }
        }
        __syncthreads();

        // LSTM cell: thread owns (b_local = eb0 + 16p, unit = eu)
#pragma unroll
        for (int p = 0; p < 4; ++p) {
            int bl = eb0 + p * 16;
            float gi = gsm[bl * GSM_STRIDE + eu]        + bias_s[eu];
            float gf = gsm[bl * GSM_STRIDE + 16 + eu]   + bias_s[16 + eu];
            float gg = gsm[bl * GSM_STRIDE + 32 + eu]   + bias_s[32 + eu];
            float go = gsm[bl * GSM_STRIDE + 48 + eu]   + bias_s[48 + eu];
            float ii = sigmoidf_(gi);
            float ff = sigmoidf_(gf);
            float gt = tanhf_(gg);
            float oo = sigmoidf_(go);
            float cn = ff * creg[p] + ii * gt;
            float hn = oo * tanhf_(cn);
            bool  m  = t < len_s[bl];
            float h2 = m ? hn : hreg[p];
            creg[p]  = m ? cn : creg[p];
            hreg[p]  = h2;
            __nv_bfloat16 hb = __float2bfloat16(h2);
            int bg = b0 + bl;
            int j  = hid0 + eu;
            h_nxt[bg * HID + j] = hb;
            g_Hall[((size_t)t * BATCH + bg) * HID + j] = hb;
        }

        // publish step t
        __threadfence();
        __syncthreads();
        if (tid == 0) __stcg(&g_flag[bid << 2], t + 1);
    }
}

// ---------------- FC head: logits + binary expansion ----------------
__global__ void __launch_bounds__(128)
fc_kernel(const int* __restrict__ lens, const float* __restrict__ bfc,
          float* __restrict__ out)
{
    __shared__ __nv_bfloat16 As[64 * FC_ASTR];
    __shared__ __nv_bfloat16 Bs[88 * FC_ASTR];

    const int tid  = threadIdx.x;
    const int lane = tid & 31, wid = tid >> 5;
    const int r0   = blockIdx.x * 64;   // rows of H_all (tb = t*128 + b)

    float acc[11][4];
#pragma unroll
    for (int i = 0; i < 11; ++i)
#pragma unroll
        for (int j = 0; j < 4; ++j) acc[i][j] = 0.f;

    const unsigned as_u = smem_u32(As);
    const unsigned bs_u = smem_u32(Bs);

    for (int ch = 0; ch < 16; ++ch) {
        __syncthreads();
        const int k0 = ch * 64;
        for (int i = tid; i < 512; i += 128) {          // A: 64 rows x 8 uint4
            int row = i >> 3, c8 = i & 7;
            uint4 v = *(reinterpret_cast<const uint4*>(
                    g_Hall + (size_t)(r0 + row) * HID + k0) + c8);
            *(reinterpret_cast<uint4*>(As + row * FC_ASTR) + c8) = v;
        }
        for (int i = tid; i < 704; i += 128) {          // B: 88 rows x 8 uint4
            int row = i >> 3, c8 = i & 7;
            uint4 v = *(reinterpret_cast<const uint4*>(
                    g_Wfcb + (size_t)row * HID + k0) + c8);
            *(reinterpret_cast<uint4*>(Bs + row * FC_ASTR) + c8) = v;
        }
        __syncthreads();
#pragma unroll
        for (int ks = 0; ks < 4; ++ks) {
            int kk = ks * 16;
            unsigned a0, a1, a2, a3;
            unsigned addr = as_u +
                (unsigned)(((wid * 16 + (lane & 15)) * FC_ASTR + kk + ((lane >> 4) << 3)) * 2);
            LDMATRIX_X4(a0, a1, a2, a3, addr);
#pragma unroll
            for (int nf = 0; nf < 11; ++nf) {
                int n = nf * 8 + (lane >> 2);
                unsigned baddr = bs_u +
                    (unsigned)((n * FC_ASTR + kk + ((lane & 3) << 1)) * 2);
                unsigned b0r, b1r;
                asm volatile("ld.shared.b32 %0, [%1];" : "=r"(b0r) : "r"(baddr));
                asm volatile("ld.shared.b32 %0, [%1];" : "=r"(b1r) : "r"(baddr + 16));
                MMA_BF16(acc[nf], a0, a1, a2, a3, b0r, b1r);
            }
        }
    }

#pragma unroll
    for (int half = 0; half < 2; ++half) {
        int r  = wid * 16 + (lane >> 2) + half * 8;
        int tb = r0 + r;
        int t  = tb >> 7;
        int b  = tb & 127;
        bool m = t < __ldg(lens + b);
        size_t obase = ((size_t)b * T_STEPS + t) * CLS * 2;
#pragma unroll
        for (int nf = 0; nf < 11; ++nf) {
            int c = nf * 8 + ((lane & 3) << 1);
            float l0 = acc[nf][half * 2 + 0] + __ldg(bfc + c);
            float l1 = acc[nf][half * 2 + 1] + __ldg(bfc + c + 1);
            if (!m) { l0 = 0.f; l1 = 0.f; }
            float4 v = make_float4(l0, 1.f - l0, l1, 1.f - l1);
            *reinterpret_cast<float4*>(out + obase + (size_t)c * 2) = v;
        }
    }
}

// ---------------- launch ----------------
extern "C" void kernel_launch(void* const* d_in, const int* in_sizes, int n_in,
                              void* d_out, int out_size) {
    const float* x    = (const float*)d_in[0];
    const int*   lens = (const int*)d_in[1];    // int32 (JAX x64 disabled)
    const float* Wih  = (const float*)d_in[2];
    const float* Whh  = (const float*)d_in[3];
    const float* bih  = (const float*)d_in[4];
    const float* bhh  = (const float*)d_in[5];
    const float* Wfc  = (const float*)d_in[6];
    const float* bfc  = (const float*)d_in[7];
    float*       out  = (float*)d_out;
    (void)in_sizes; (void)n_in; (void)out_size;

    // launch order chosen so lstm_kernel is the 4th launch (ncu capture slot)
    init_kernel<<<64, 256>>>();
    {
        size_t tot = (size_t)4096 * KP;
        prep_all_kernel<<<(unsigned)((tot + 255) / 256), 256>>>(Wih, Whh, bih, bhh, Wfc);
    }
    {
        size_t tot = (size_t)T_STEPS * BATCH * FEAT;
        prep_x_kernel<<<(unsigned)((tot + 255) / 256), 256>>>(x);
    }

    int smem = 64 * WS_STRIDE * 2          // resident W slice   (149504)
             + NBUF * 64 * ASTR * 2        // A-stage ring       (69632)
             + 64 * 4 + 64 * 4;            // bias + lengths
    cudaFuncSetAttribute(lstm_kernel, cudaFuncAttributeMaxDynamicSharedMemorySize, smem);
    lstm_kernel<<<NCTA, NTHR, smem>>>(lens);

    fc_kernel<<<(T_STEPS * BATCH) / 64, 128>>>(lens, bfc, out);
}